// round 15
// baseline (speedup 1.0000x reference)
#include <cuda_runtime.h>
#include <cstdint>

// RelationalModule, full-fp16 datapath: packed-permuted f16 embeddings,
// m16n8k16 f16 C/D MMAs, HADD2/HMAX2 activation math, 3 CTAs/SM.
// Inputs: 0 x_img(64*1600) 1 W0(130*32) 2 b0 3 W1 4 b1 5 W2 6 b2 7 Wp 8 bp 9 Wo 10 bo
// Output: 32 f32.

#define N_PIX 1600
#define HID   32
#define NJT   (N_PIX / 32)          // 50 j-tiles
#define NUNIT (NJT * N_PIX)         // 80,000 units (1 i x 32 j each)
#define NCTA  444                   // 3 CTAs/SM x 148, one wave
#define WPC   4
#define NW    (NCTA * WPC)          // 1776 warps

// packed f16, permuted so thread t's 4 words per row are uint4 #t:
// word w = t*4+q holds k-pair (q&1)*8 + (q>>1)*16 + 2t (lo), +1 (hi)
__device__ __align__(16) unsigned short g_ah[N_PIX * HID];
__device__ __align__(16) unsigned short g_bh[N_PIX * HID];   // includes +b0
__device__ __align__(16) float g_part[NW * HID];

// ---------------------------------------------------------------------------
// helpers
// ---------------------------------------------------------------------------
__device__ __forceinline__ uint32_t hadd2(uint32_t a, uint32_t b) {
    uint32_t d; asm("add.f16x2 %0,%1,%2;" : "=r"(d) : "r"(a), "r"(b)); return d;
}
__device__ __forceinline__ uint32_t hrelu2(uint32_t a) {
    uint32_t d; asm("max.f16x2 %0,%1,%2;" : "=r"(d) : "r"(a), "r"(0u)); return d;
}
__device__ __forceinline__ uint32_t packH(float x0, float x1) {
    uint32_t h;
    asm("cvt.rn.f16x2.f32 %0, %1, %2;" : "=r"(h) : "f"(x1), "f"(x0));
    return h;
}
__device__ __forceinline__ void unpackH(uint32_t v, float& lo, float& hi) {
    asm("{.reg .f16 l,h; mov.b32 {l,h}, %2; cvt.f32.f16 %0, l; cvt.f32.f16 %1, h;}"
        : "=f"(lo), "=f"(hi) : "r"(v));
}
// f16 C/D mma: {d0,d1} = A@B + {c0,c1}
__device__ __forceinline__ void mmaH(uint32_t& d0, uint32_t& d1,
                                     const uint32_t* a, const uint32_t* b,
                                     uint32_t c0, uint32_t c1) {
    asm("mma.sync.aligned.m16n8k16.row.col.f16.f16.f16.f16 "
        "{%0,%1}, {%2,%3,%4,%5}, {%6,%7}, {%8,%9};"
        : "=r"(d0), "=r"(d1)
        : "r"(a[0]), "r"(a[1]), "r"(a[2]), "r"(a[3]), "r"(b[0]), "r"(b[1]),
          "r"(c0), "r"(c1));
}

// ---------------------------------------------------------------------------
// Phase 0: per-pixel embeddings -> permuted packed f16. 8-way channel split.
// thread t: c = t&7 (8 channels each), k = (t>>3)&31, n = t>>8.
// ---------------------------------------------------------------------------
__global__ void precompute_ab(const float* __restrict__ x,
                              const float* __restrict__ W0,
                              const float* __restrict__ b0) {
    int t = blockIdx.x * blockDim.x + threadIdx.x;
    if (t >= N_PIX * HID * 8) return;
    int c = t & 7;
    int k = (t >> 3) & 31;
    int n = t >> 8;
    float fa = 0.f, fb = 0.f;
    int ch0 = c * 8;
#pragma unroll
    for (int q = 0; q < 8; q++) {
        int ch = ch0 + q;
        float xv = x[ch * N_PIX + n];
        fa = fmaf(xv, W0[ch * HID + k], fa);
        fb = fmaf(xv, W0[(65 + ch) * HID + k], fb);
    }
    if (c == 0) {
        float cf = (float)n;
        fa = fmaf(cf, W0[64 * HID + k], fa);
        fb = fmaf(cf, W0[129 * HID + k], fb);
    }
#pragma unroll
    for (int o = 1; o < 8; o <<= 1) {
        fa += __shfl_xor_sync(0xffffffffu, fa, o);
        fb += __shfl_xor_sync(0xffffffffu, fb, o);
    }
    if (c == 0) {
        int p = k >> 1;
        int pos = ((p & 3) * 4 + (p >> 2)) * 2 + (k & 1);
        unsigned short ha, hb;
        asm("cvt.rn.f16.f32 %0, %1;" : "=h"(ha) : "f"(fa));
        float fbb = fb + b0[k];
        asm("cvt.rn.f16.f32 %0, %1;" : "=h"(hb) : "f"(fbb));
        g_ah[n * HID + pos] = ha;
        g_bh[n * HID + pos] = hb;
    }
}

// ---------------------------------------------------------------------------
// Phase 1: pair MLP, f16 end-to-end. 32 MMAs/unit, ~105 scalar issues/unit.
// 3 CTAs/SM (reg cap 168; body uses ~110 — no spills).
// ---------------------------------------------------------------------------
__global__ void __launch_bounds__(128, 3)
pair_kernel(const float* __restrict__ W1, const float* __restrict__ b1,
            const float* __restrict__ W2, const float* __restrict__ b2) {
    int lane = threadIdx.x & 31;
    int warp = threadIdx.x >> 5;
    int g = lane >> 2;              // 0..7
    int t = lane & 3;               // 0..3
    int w = blockIdx.x * WPC + warp;

    // ---- B fragments (fp16 weights, both layers) ----
    uint32_t B1h[2][4][2], B2h[2][4][2];
#pragma unroll
    for (int kbk = 0; kbk < 2; kbk++)
#pragma unroll
        for (int nt = 0; nt < 4; nt++)
#pragma unroll
            for (int r = 0; r < 2; r++) {
                int n = 8 * nt + g;
                int k0 = kbk * 16 + r * 8 + 2 * t;
                B1h[kbk][nt][r] = packH(W1[k0 * HID + n], W1[(k0 + 1) * HID + n]);
                B2h[kbk][nt][r] = packH(W2[k0 * HID + n], W2[(k0 + 1) * HID + n]);
            }
    // biases packed f16x2 at this lane's cols (2t, 2t+1) per nt
    uint32_t bias1p[4], bias2p[4];
#pragma unroll
    for (int nt = 0; nt < 4; nt++) {
        bias1p[nt] = packH(b1[8 * nt + 2 * t], b1[8 * nt + 2 * t + 1]);
        bias2p[nt] = packH(b2[8 * nt + 2 * t], b2[8 * nt + 2 * t + 1]);
    }

    float accE[4], accO[4];
#pragma unroll
    for (int nt = 0; nt < 4; nt++) { accE[nt] = 0.f; accO[nt] = 0.f; }

    const uint4* ga4 = (const uint4*)g_ah;   // 4 uint4 per row
    const uint4* gb4 = (const uint4*)g_bh;

    int u0 = (int)(((long long)w * NUNIT) / NW);
    int u1 = (int)(((long long)(w + 1) * NUNIT) / NW);
    int u  = u0;
    int jt = u0 / N_PIX;
    int i  = u0 - jt * N_PIX;

    while (u < u1) {
        int segEnd = (jt + 1) * N_PIX;
        if (segEnd > u1) segEnd = u1;
        int j0 = jt * 32;

        // ---- hoisted a-rows (packed): [mt][row] one uint4 each ----
        uint4 av[2][2];
#pragma unroll
        for (int mt = 0; mt < 2; mt++) {
            int ra = j0 + mt * 16 + g;
            av[mt][0] = ga4[ra * 4 + t];
            av[mt][1] = ga4[(ra + 8) * 4 + t];
        }

        uint4 bvp = gb4[i * 4 + t];   // prefetch

        for (; u < segEnd; ) {
            uint4 bv = bvp;
            u++;
            int inext = (u < segEnd) ? (i + 1) : i;
            bvp = gb4[inext * 4 + t];

            // ---- h0 = relu(a+b), already fragment-ordered ----
            uint32_t A[2][2][4];
#pragma unroll
            for (int mt = 0; mt < 2; mt++) {
                A[mt][0][0] = hrelu2(hadd2(av[mt][0].x, bv.x));
                A[mt][0][1] = hrelu2(hadd2(av[mt][1].x, bv.x));
                A[mt][0][2] = hrelu2(hadd2(av[mt][0].y, bv.y));
                A[mt][0][3] = hrelu2(hadd2(av[mt][1].y, bv.y));
                A[mt][1][0] = hrelu2(hadd2(av[mt][0].z, bv.z));
                A[mt][1][1] = hrelu2(hadd2(av[mt][1].z, bv.z));
                A[mt][1][2] = hrelu2(hadd2(av[mt][0].w, bv.w));
                A[mt][1][3] = hrelu2(hadd2(av[mt][1].w, bv.w));
            }

            // ---- layer 1 (f16 D), bias via C ----
            uint32_t D[2][4][2];
#pragma unroll
            for (int mt = 0; mt < 2; mt++)
#pragma unroll
                for (int nt = 0; nt < 4; nt++) {
                    mmaH(D[mt][nt][0], D[mt][nt][1], A[mt][0], B1h[0][nt],
                         bias1p[nt], bias1p[nt]);
                    mmaH(D[mt][nt][0], D[mt][nt][1], A[mt][1], B1h[1][nt],
                         D[mt][nt][0], D[mt][nt][1]);
                }

            // ---- h1 = relu(D): HMAX2 + register renaming (C->A identity) ----
#pragma unroll
            for (int mt = 0; mt < 2; mt++) {
                A[mt][0][0] = hrelu2(D[mt][0][0]);
                A[mt][0][1] = hrelu2(D[mt][0][1]);
                A[mt][0][2] = hrelu2(D[mt][1][0]);
                A[mt][0][3] = hrelu2(D[mt][1][1]);
                A[mt][1][0] = hrelu2(D[mt][2][0]);
                A[mt][1][1] = hrelu2(D[mt][2][1]);
                A[mt][1][2] = hrelu2(D[mt][3][0]);
                A[mt][1][3] = hrelu2(D[mt][3][1]);
            }

            // ---- layer 2 (f16 D), bias via C ----
#pragma unroll
            for (int mt = 0; mt < 2; mt++)
#pragma unroll
                for (int nt = 0; nt < 4; nt++) {
                    mmaH(D[mt][nt][0], D[mt][nt][1], A[mt][0], B2h[0][nt],
                         bias2p[nt], bias2p[nt]);
                    mmaH(D[mt][nt][0], D[mt][nt][1], A[mt][1], B2h[1][nt],
                         D[mt][nt][0], D[mt][nt][1]);
                }

            // ---- acc += relu(D2): fold 4 row-groups in f16, then 2 cvt+add ----
#pragma unroll
            for (int nt = 0; nt < 4; nt++) {
                uint32_t s01 = hadd2(hrelu2(D[0][nt][0]), hrelu2(D[0][nt][1]));
                uint32_t s23 = hadd2(hrelu2(D[1][nt][0]), hrelu2(D[1][nt][1]));
                uint32_t s = hadd2(s01, s23);
                float lo, hi;
                unpackH(s, lo, hi);
                accE[nt] += lo;
                accO[nt] += hi;
            }

            i++;
        }
        if (u < u1) { jt++; i = 0; }
    }

    // ---- reduce over the 8 g-groups (t fixed) ----
#pragma unroll
    for (int nt = 0; nt < 4; nt++) {
#pragma unroll
        for (int o = 4; o < 32; o <<= 1) {
            accE[nt] += __shfl_xor_sync(0xffffffffu, accE[nt], o);
            accO[nt] += __shfl_xor_sync(0xffffffffu, accO[nt], o);
        }
    }
    if (lane < 4) {
#pragma unroll
        for (int nt = 0; nt < 4; nt++) {
            g_part[w * HID + 8 * nt + 2 * lane + 0] = accE[nt];
            g_part[w * HID + 8 * nt + 2 * lane + 1] = accO[nt];
        }
    }
}

// ---------------------------------------------------------------------------
// Phase 2: reduce 1776 partials -> s[32]; head MLP -> out[32]
// ---------------------------------------------------------------------------
__global__ void reduce_out(const float* __restrict__ Wp, const float* __restrict__ bp,
                           const float* __restrict__ Wo, const float* __restrict__ bo,
                           float* __restrict__ out) {
    __shared__ float tmp[8][HID];
    __shared__ float s[HID], pvec[HID];
    int tid = threadIdx.x;              // 256
    int k = tid & 31, grp = tid >> 5;
    float lsum = 0.f;
    for (int b = grp; b < NW; b += 8)
        lsum += g_part[b * HID + k];
    tmp[grp][k] = lsum;
    __syncthreads();
    if (tid < HID) {
        float t = 0.f;
#pragma unroll
        for (int gg = 0; gg < 8; gg++) t += tmp[gg][tid];
        s[tid] = t;
    }
    __syncthreads();
    if (tid < HID) {
        float t = bp[tid];
#pragma unroll
        for (int kk = 0; kk < HID; kk++) t = fmaf(s[kk], Wp[kk * HID + tid], t);
        pvec[tid] = fmaxf(t, 0.f);
    }
    __syncthreads();
    if (tid < HID) {
        float t = bo[tid];
#pragma unroll
        for (int kk = 0; kk < HID; kk++) t = fmaf(pvec[kk], Wo[kk * HID + tid], t);
        out[tid] = t;
    }
}

// ---------------------------------------------------------------------------
extern "C" void kernel_launch(void* const* d_in, const int* in_sizes, int n_in,
                              void* d_out, int out_size) {
    const float* x  = (const float*)d_in[0];
    const float* W0 = (const float*)d_in[1];
    const float* b0 = (const float*)d_in[2];
    const float* W1 = (const float*)d_in[3];
    const float* b1 = (const float*)d_in[4];
    const float* W2 = (const float*)d_in[5];
    const float* b2 = (const float*)d_in[6];
    const float* Wp = (const float*)d_in[7];
    const float* bp = (const float*)d_in[8];
    const float* Wo = (const float*)d_in[9];
    const float* bo = (const float*)d_in[10];
    float* out = (float*)d_out;

    precompute_ab<<<(N_PIX * HID * 8 + 255) / 256, 256>>>(x, W0, b0);
    pair_kernel<<<NCTA, 128>>>(W1, b1, W2, b2);
    reduce_out<<<1, 256>>>(Wp, bp, Wo, bo, out);
}

// round 16
// speedup vs baseline: 1.1411x; 1.1411x over previous
#include <cuda_runtime.h>
#include <cstdint>

// RelationalModule, full-fp16 datapath (R14 pair kernel, proven 36.7us) +
// smem-staged precompute GEMM + wide reduce.
// Inputs: 0 x_img(64*1600) 1 W0(130*32) 2 b0 3 W1 4 b1 5 W2 6 b2 7 Wp 8 bp 9 Wo 10 bo
// Output: 32 f32.

#define N_PIX 1600
#define HID   32
#define NJT   (N_PIX / 32)          // 50 j-tiles
#define NUNIT (NJT * N_PIX)         // 80,000 units (1 i x 32 j each)
#define NCTA  296                   // 2 CTAs/SM (proven best)
#define WPC   4
#define NW    (NCTA * WPC)          // 1184 warps

// packed f16, permuted so thread t's 4 words per row are uint4 #t:
// word w = t*4+q holds k-pair (q&1)*8 + (q>>1)*16 + 2t (lo), +1 (hi)
__device__ __align__(16) unsigned short g_ah[N_PIX * HID];
__device__ __align__(16) unsigned short g_bh[N_PIX * HID];   // includes +b0
__device__ __align__(16) float g_part[NW * HID];

// ---------------------------------------------------------------------------
// helpers
// ---------------------------------------------------------------------------
__device__ __forceinline__ uint32_t hadd2(uint32_t a, uint32_t b) {
    uint32_t d; asm("add.f16x2 %0,%1,%2;" : "=r"(d) : "r"(a), "r"(b)); return d;
}
__device__ __forceinline__ uint32_t hrelu2(uint32_t a) {
    uint32_t d; asm("max.f16x2 %0,%1,%2;" : "=r"(d) : "r"(a), "r"(0u)); return d;
}
__device__ __forceinline__ uint32_t packH(float x0, float x1) {
    uint32_t h;
    asm("cvt.rn.f16x2.f32 %0, %1, %2;" : "=r"(h) : "f"(x1), "f"(x0));
    return h;
}
__device__ __forceinline__ void unpackH(uint32_t v, float& lo, float& hi) {
    asm("{.reg .f16 l,h; mov.b32 {l,h}, %2; cvt.f32.f16 %0, l; cvt.f32.f16 %1, h;}"
        : "=f"(lo), "=f"(hi) : "r"(v));
}
// f16 C/D mma: {d0,d1} = A@B + {c0,c1}
__device__ __forceinline__ void mmaH(uint32_t& d0, uint32_t& d1,
                                     const uint32_t* a, const uint32_t* b,
                                     uint32_t c0, uint32_t c1) {
    asm("mma.sync.aligned.m16n8k16.row.col.f16.f16.f16.f16 "
        "{%0,%1}, {%2,%3,%4,%5}, {%6,%7}, {%8,%9};"
        : "=r"(d0), "=r"(d1)
        : "r"(a[0]), "r"(a[1]), "r"(a[2]), "r"(a[3]), "r"(b[0]), "r"(b[1]),
          "r"(c0), "r"(c1));
}

// ---------------------------------------------------------------------------
// Phase 0: smem-staged mini-GEMM. 50 CTAs x 128 thr; CTA owns 32 pixels.
// thread: nl = tid&31 (pixel), kq = tid>>2? no: kq = tid>>5 (8 k's).
// ---------------------------------------------------------------------------
__global__ void __launch_bounds__(128)
precompute_ab(const float* __restrict__ x,
              const float* __restrict__ W0,
              const float* __restrict__ b0) {
    __shared__ float sW[130 * 32];       // W0 staged (Wa rows 0..64, Wb 65..129)
    __shared__ float sx[64][32];         // x slab: 64 ch x 32 pixels

    int tid = threadIdx.x;
    int n0 = blockIdx.x * 32;

    for (int idx = tid; idx < 130 * 32; idx += 128)
        sW[idx] = W0[idx];
    for (int idx = tid; idx < 64 * 32; idx += 128) {
        int ch = idx >> 5, nl = idx & 31;
        sx[ch][nl] = x[ch * N_PIX + n0 + nl];
    }
    __syncthreads();

    int nl = tid & 31;
    int kq = tid >> 5;               // 0..3
    int k0 = kq * 8;

    float fa[8], fb[8];
#pragma unroll
    for (int q = 0; q < 8; q++) { fa[q] = 0.f; fb[q] = 0.f; }

#pragma unroll 8
    for (int ch = 0; ch < 64; ch++) {
        float xv = sx[ch][nl];
        const float* wa = sW + ch * 32 + k0;
        const float* wb = sW + (65 + ch) * 32 + k0;
#pragma unroll
        for (int q = 0; q < 8; q++) {
            fa[q] = fmaf(xv, wa[q], fa[q]);
            fb[q] = fmaf(xv, wb[q], fb[q]);
        }
    }
    {
        float cf = (float)(n0 + nl);
        const float* wa = sW + 64 * 32 + k0;
        const float* wb = sW + 129 * 32 + k0;
#pragma unroll
        for (int q = 0; q < 8; q++) {
            fa[q] = fmaf(cf, wa[q], fa[q]);
            fb[q] = fmaf(cf, wb[q], fb[q]) + b0[k0 + q];
        }
    }
    int n = n0 + nl;
#pragma unroll
    for (int q = 0; q < 8; q++) {
        int k = k0 + q;
        int p = k >> 1;
        int pos = ((p & 3) * 4 + (p >> 2)) * 2 + (k & 1);
        unsigned short ha, hb;
        asm("cvt.rn.f16.f32 %0, %1;" : "=h"(ha) : "f"(fa[q]));
        asm("cvt.rn.f16.f32 %0, %1;" : "=h"(hb) : "f"(fb[q]));
        g_ah[n * HID + pos] = ha;
        g_bh[n * HID + pos] = hb;
    }
}

// ---------------------------------------------------------------------------
// Phase 1: pair MLP, f16 end-to-end (identical to R14 best).
// ---------------------------------------------------------------------------
__global__ void __launch_bounds__(128)
pair_kernel(const float* __restrict__ W1, const float* __restrict__ b1,
            const float* __restrict__ W2, const float* __restrict__ b2) {
    int lane = threadIdx.x & 31;
    int warp = threadIdx.x >> 5;
    int g = lane >> 2;              // 0..7
    int t = lane & 3;               // 0..3
    int w = blockIdx.x * WPC + warp;

    uint32_t B1h[2][4][2], B2h[2][4][2];
#pragma unroll
    for (int kbk = 0; kbk < 2; kbk++)
#pragma unroll
        for (int nt = 0; nt < 4; nt++)
#pragma unroll
            for (int r = 0; r < 2; r++) {
                int n = 8 * nt + g;
                int k0 = kbk * 16 + r * 8 + 2 * t;
                B1h[kbk][nt][r] = packH(W1[k0 * HID + n], W1[(k0 + 1) * HID + n]);
                B2h[kbk][nt][r] = packH(W2[k0 * HID + n], W2[(k0 + 1) * HID + n]);
            }
    uint32_t bias1p[4], bias2p[4];
#pragma unroll
    for (int nt = 0; nt < 4; nt++) {
        bias1p[nt] = packH(b1[8 * nt + 2 * t], b1[8 * nt + 2 * t + 1]);
        bias2p[nt] = packH(b2[8 * nt + 2 * t], b2[8 * nt + 2 * t + 1]);
    }

    float accE[4], accO[4];
#pragma unroll
    for (int nt = 0; nt < 4; nt++) { accE[nt] = 0.f; accO[nt] = 0.f; }

    const uint4* ga4 = (const uint4*)g_ah;
    const uint4* gb4 = (const uint4*)g_bh;

    int u0 = (int)(((long long)w * NUNIT) / NW);
    int u1 = (int)(((long long)(w + 1) * NUNIT) / NW);
    int u  = u0;
    int jt = u0 / N_PIX;
    int i  = u0 - jt * N_PIX;

    while (u < u1) {
        int segEnd = (jt + 1) * N_PIX;
        if (segEnd > u1) segEnd = u1;
        int j0 = jt * 32;

        uint4 av[2][2];
#pragma unroll
        for (int mt = 0; mt < 2; mt++) {
            int ra = j0 + mt * 16 + g;
            av[mt][0] = ga4[ra * 4 + t];
            av[mt][1] = ga4[(ra + 8) * 4 + t];
        }

        uint4 bvp = gb4[i * 4 + t];

        for (; u < segEnd; ) {
            uint4 bv = bvp;
            u++;
            int inext = (u < segEnd) ? (i + 1) : i;
            bvp = gb4[inext * 4 + t];

            uint32_t A[2][2][4];
#pragma unroll
            for (int mt = 0; mt < 2; mt++) {
                A[mt][0][0] = hrelu2(hadd2(av[mt][0].x, bv.x));
                A[mt][0][1] = hrelu2(hadd2(av[mt][1].x, bv.x));
                A[mt][0][2] = hrelu2(hadd2(av[mt][0].y, bv.y));
                A[mt][0][3] = hrelu2(hadd2(av[mt][1].y, bv.y));
                A[mt][1][0] = hrelu2(hadd2(av[mt][0].z, bv.z));
                A[mt][1][1] = hrelu2(hadd2(av[mt][1].z, bv.z));
                A[mt][1][2] = hrelu2(hadd2(av[mt][0].w, bv.w));
                A[mt][1][3] = hrelu2(hadd2(av[mt][1].w, bv.w));
            }

            uint32_t D[2][4][2];
#pragma unroll
            for (int mt = 0; mt < 2; mt++)
#pragma unroll
                for (int nt = 0; nt < 4; nt++) {
                    mmaH(D[mt][nt][0], D[mt][nt][1], A[mt][0], B1h[0][nt],
                         bias1p[nt], bias1p[nt]);
                    mmaH(D[mt][nt][0], D[mt][nt][1], A[mt][1], B1h[1][nt],
                         D[mt][nt][0], D[mt][nt][1]);
                }

#pragma unroll
            for (int mt = 0; mt < 2; mt++) {
                A[mt][0][0] = hrelu2(D[mt][0][0]);
                A[mt][0][1] = hrelu2(D[mt][0][1]);
                A[mt][0][2] = hrelu2(D[mt][1][0]);
                A[mt][0][3] = hrelu2(D[mt][1][1]);
                A[mt][1][0] = hrelu2(D[mt][2][0]);
                A[mt][1][1] = hrelu2(D[mt][2][1]);
                A[mt][1][2] = hrelu2(D[mt][3][0]);
                A[mt][1][3] = hrelu2(D[mt][3][1]);
            }

#pragma unroll
            for (int mt = 0; mt < 2; mt++)
#pragma unroll
                for (int nt = 0; nt < 4; nt++) {
                    mmaH(D[mt][nt][0], D[mt][nt][1], A[mt][0], B2h[0][nt],
                         bias2p[nt], bias2p[nt]);
                    mmaH(D[mt][nt][0], D[mt][nt][1], A[mt][1], B2h[1][nt],
                         D[mt][nt][0], D[mt][nt][1]);
                }

#pragma unroll
            for (int nt = 0; nt < 4; nt++) {
                uint32_t s01 = hadd2(hrelu2(D[0][nt][0]), hrelu2(D[0][nt][1]));
                uint32_t s23 = hadd2(hrelu2(D[1][nt][0]), hrelu2(D[1][nt][1]));
                uint32_t s = hadd2(s01, s23);
                float lo, hi;
                unpackH(s, lo, hi);
                accE[nt] += lo;
                accO[nt] += hi;
            }

            i++;
        }
        if (u < u1) { jt++; i = 0; }
    }

#pragma unroll
    for (int nt = 0; nt < 4; nt++) {
#pragma unroll
        for (int o = 4; o < 32; o <<= 1) {
            accE[nt] += __shfl_xor_sync(0xffffffffu, accE[nt], o);
            accO[nt] += __shfl_xor_sync(0xffffffffu, accO[nt], o);
        }
    }
    if (lane < 4) {
#pragma unroll
        for (int nt = 0; nt < 4; nt++) {
            g_part[w * HID + 8 * nt + 2 * lane + 0] = accE[nt];
            g_part[w * HID + 8 * nt + 2 * lane + 1] = accO[nt];
        }
    }
}

// ---------------------------------------------------------------------------
// Phase 2: reduce 1184 partials (1024 threads, 32 groups) + head MLP.
// ---------------------------------------------------------------------------
__global__ void __launch_bounds__(1024)
reduce_out(const float* __restrict__ Wp, const float* __restrict__ bp,
           const float* __restrict__ Wo, const float* __restrict__ bo,
           float* __restrict__ out) {
    __shared__ float tmp[32][HID];
    __shared__ float s[HID], pvec[HID];
    int tid = threadIdx.x;              // 1024
    int k = tid & 31, grp = tid >> 5;   // 32 groups of 32
    float lsum = 0.f;
    for (int b = grp; b < NW; b += 32)
        lsum += g_part[b * HID + k];
    tmp[grp][k] = lsum;
    __syncthreads();
    if (tid < HID) {
        float t = 0.f;
#pragma unroll
        for (int gg = 0; gg < 32; gg++) t += tmp[gg][tid];
        s[tid] = t;
    }
    __syncthreads();
    if (tid < HID) {
        float t = bp[tid];
#pragma unroll
        for (int kk = 0; kk < HID; kk++) t = fmaf(s[kk], Wp[kk * HID + tid], t);
        pvec[tid] = fmaxf(t, 0.f);
    }
    __syncthreads();
    if (tid < HID) {
        float t = bo[tid];
#pragma unroll
        for (int kk = 0; kk < HID; kk++) t = fmaf(pvec[kk], Wo[kk * HID + tid], t);
        out[tid] = t;
    }
}

// ---------------------------------------------------------------------------
extern "C" void kernel_launch(void* const* d_in, const int* in_sizes, int n_in,
                              void* d_out, int out_size) {
    const float* x  = (const float*)d_in[0];
    const float* W0 = (const float*)d_in[1];
    const float* b0 = (const float*)d_in[2];
    const float* W1 = (const float*)d_in[3];
    const float* b1 = (const float*)d_in[4];
    const float* W2 = (const float*)d_in[5];
    const float* b2 = (const float*)d_in[6];
    const float* Wp = (const float*)d_in[7];
    const float* bp = (const float*)d_in[8];
    const float* Wo = (const float*)d_in[9];
    const float* bo = (const float*)d_in[10];
    float* out = (float*)d_out;

    precompute_ab<<<N_PIX / 32, 128>>>(x, W0, b0);
    pair_kernel<<<NCTA, 128>>>(W1, b1, W2, b2);
    reduce_out<<<1, 1024>>>(Wp, bp, Wo, bo, out);
}

// round 17
// speedup vs baseline: 1.1584x; 1.0152x over previous
#include <cuda_runtime.h>
#include <cstdint>

// RelationalModule: ONE persistent fused kernel (embed -> grid barrier ->
// pair MLP on fp16 mma.sync -> grid barrier -> 2-level reduce + head).
// Inputs: 0 x_img(64*1600) 1 W0(130*32) 2 b0 3 W1 4 b1 5 W2 6 b2 7 Wp 8 bp 9 Wo 10 bo
// Output: 32 f32.

#define N_PIX 1600
#define HID   32
#define NJT   (N_PIX / 32)
#define NUNIT (NJT * N_PIX)          // 80,000 units (1 i x 32 j)
#define NCTA  296                    // 2 CTAs/SM x 148 = one wave (co-resident)
#define WPC   4
#define NW    (NCTA * WPC)           // 1184 warps

// packed f16, permuted: thread t's 4 words per row form uint4 #t
__device__ __align__(16) unsigned short g_ah[N_PIX * HID];
__device__ __align__(16) unsigned short g_bh[N_PIX * HID];   // includes +b0
__device__ __align__(16) float g_part[NW * HID];
__device__ __align__(16) float g_q[32 * HID];
__device__ int g_count = 0;
__device__ volatile int g_sense = 0;

// ---------------------------------------------------------------------------
// helpers
// ---------------------------------------------------------------------------
__device__ __forceinline__ uint32_t hadd2(uint32_t a, uint32_t b) {
    uint32_t d; asm("add.f16x2 %0,%1,%2;" : "=r"(d) : "r"(a), "r"(b)); return d;
}
__device__ __forceinline__ uint32_t hrelu2(uint32_t a) {
    uint32_t d; asm("max.f16x2 %0,%1,%2;" : "=r"(d) : "r"(a), "r"(0u)); return d;
}
__device__ __forceinline__ uint32_t packH(float x0, float x1) {
    uint32_t h;
    asm("cvt.rn.f16x2.f32 %0, %1, %2;" : "=r"(h) : "f"(x1), "f"(x0));
    return h;
}
__device__ __forceinline__ void unpackH(uint32_t v, float& lo, float& hi) {
    asm("{.reg .f16 l,h; mov.b32 {l,h}, %2; cvt.f32.f16 %0, l; cvt.f32.f16 %1, h;}"
        : "=f"(lo), "=f"(hi) : "r"(v));
}
__device__ __forceinline__ void mmaH(uint32_t& d0, uint32_t& d1,
                                     const uint32_t* a, const uint32_t* b,
                                     uint32_t c0, uint32_t c1) {
    asm("mma.sync.aligned.m16n8k16.row.col.f16.f16.f16.f16 "
        "{%0,%1}, {%2,%3,%4,%5}, {%6,%7}, {%8,%9};"
        : "=r"(d0), "=r"(d1)
        : "r"(a[0]), "r"(a[1]), "r"(a[2]), "r"(a[3]), "r"(b[0]), "r"(b[1]),
          "r"(c0), "r"(c1));
}

// sense-reversing grid barrier; requires all NCTA CTAs co-resident.
// Self-resetting (count back to 0 before sense flips) -> graph-replay safe.
__device__ __forceinline__ void grid_barrier(int tid) {
    int s = g_sense;                 // read sense BEFORE arrival
    __syncthreads();                 // all CTA threads past their writes + read
    if (tid == 0) {
        __threadfence();             // release (cumulative)
        int old = atomicAdd(&g_count, 1);
        if (old == NCTA - 1) {
            g_count = 0;             // reset before release flip
            __threadfence();
            g_sense = 1 - s;         // release
        } else {
            while (g_sense == s) { } // spin (one thread per CTA)
        }
        __threadfence();             // acquire
    }
    __syncthreads();
}

// ---------------------------------------------------------------------------
__global__ void __launch_bounds__(128, 2)
fused_kernel(const float* __restrict__ x,  const float* __restrict__ W0,
             const float* __restrict__ b0, const float* __restrict__ W1,
             const float* __restrict__ b1, const float* __restrict__ W2,
             const float* __restrict__ b2, const float* __restrict__ Wp,
             const float* __restrict__ bp, const float* __restrict__ Wo,
             const float* __restrict__ bo, float* __restrict__ out) {
    __shared__ float tmpA[4][HID];
    __shared__ float sS[HID], sP[HID];

    int tid = threadIdx.x;
    int lane = tid & 31;
    int warp = tid >> 5;

    // ================= Phase 0: embeddings =================
    // item = n*32 + k; warp-uniform n (broadcast x), coalesced W0.
    for (int item = blockIdx.x * 128 + tid; item < N_PIX * HID;
         item += NCTA * 128) {
        int n = item >> 5, k = item & 31;
        float fa = 0.f, fb = 0.f;
#pragma unroll 8
        for (int ch = 0; ch < 64; ch++) {
            float xv = x[ch * N_PIX + n];
            fa = fmaf(xv, W0[ch * HID + k], fa);
            fb = fmaf(xv, W0[(65 + ch) * HID + k], fb);
        }
        float cf = (float)n;
        fa = fmaf(cf, W0[64 * HID + k], fa);
        fb = fmaf(cf, W0[129 * HID + k], fb) + b0[k];
        int p = k >> 1;
        int pos = ((p & 3) * 4 + (p >> 2)) * 2 + (k & 1);
        unsigned short ha, hb;
        asm("cvt.rn.f16.f32 %0, %1;" : "=h"(ha) : "f"(fa));
        asm("cvt.rn.f16.f32 %0, %1;" : "=h"(hb) : "f"(fb));
        g_ah[n * HID + pos] = ha;
        g_bh[n * HID + pos] = hb;
    }
    grid_barrier(tid);

    // ================= Phase 1: pair MLP (R14 proven body) =================
    {
        int g = lane >> 2;
        int t = lane & 3;
        int w = blockIdx.x * WPC + warp;

        uint32_t B1h[2][4][2], B2h[2][4][2];
#pragma unroll
        for (int kbk = 0; kbk < 2; kbk++)
#pragma unroll
            for (int nt = 0; nt < 4; nt++)
#pragma unroll
                for (int r = 0; r < 2; r++) {
                    int n = 8 * nt + g;
                    int k0 = kbk * 16 + r * 8 + 2 * t;
                    B1h[kbk][nt][r] = packH(W1[k0 * HID + n], W1[(k0 + 1) * HID + n]);
                    B2h[kbk][nt][r] = packH(W2[k0 * HID + n], W2[(k0 + 1) * HID + n]);
                }
        uint32_t bias1p[4], bias2p[4];
#pragma unroll
        for (int nt = 0; nt < 4; nt++) {
            bias1p[nt] = packH(b1[8 * nt + 2 * t], b1[8 * nt + 2 * t + 1]);
            bias2p[nt] = packH(b2[8 * nt + 2 * t], b2[8 * nt + 2 * t + 1]);
        }

        float accE[4], accO[4];
#pragma unroll
        for (int nt = 0; nt < 4; nt++) { accE[nt] = 0.f; accO[nt] = 0.f; }

        const uint4* ga4 = (const uint4*)g_ah;
        const uint4* gb4 = (const uint4*)g_bh;

        int u0 = (int)(((long long)w * NUNIT) / NW);
        int u1 = (int)(((long long)(w + 1) * NUNIT) / NW);
        int u  = u0;
        int jt = u0 / N_PIX;
        int i  = u0 - jt * N_PIX;

        while (u < u1) {
            int segEnd = (jt + 1) * N_PIX;
            if (segEnd > u1) segEnd = u1;
            int j0 = jt * 32;

            uint4 av[2][2];
#pragma unroll
            for (int mt = 0; mt < 2; mt++) {
                int ra = j0 + mt * 16 + g;
                av[mt][0] = ga4[ra * 4 + t];
                av[mt][1] = ga4[(ra + 8) * 4 + t];
            }
            uint4 bvp = gb4[i * 4 + t];

            for (; u < segEnd; ) {
                uint4 bv = bvp;
                u++;
                int inext = (u < segEnd) ? (i + 1) : i;
                bvp = gb4[inext * 4 + t];

                uint32_t A[2][2][4];
#pragma unroll
                for (int mt = 0; mt < 2; mt++) {
                    A[mt][0][0] = hrelu2(hadd2(av[mt][0].x, bv.x));
                    A[mt][0][1] = hrelu2(hadd2(av[mt][1].x, bv.x));
                    A[mt][0][2] = hrelu2(hadd2(av[mt][0].y, bv.y));
                    A[mt][0][3] = hrelu2(hadd2(av[mt][1].y, bv.y));
                    A[mt][1][0] = hrelu2(hadd2(av[mt][0].z, bv.z));
                    A[mt][1][1] = hrelu2(hadd2(av[mt][1].z, bv.z));
                    A[mt][1][2] = hrelu2(hadd2(av[mt][0].w, bv.w));
                    A[mt][1][3] = hrelu2(hadd2(av[mt][1].w, bv.w));
                }

                uint32_t D[2][4][2];
#pragma unroll
                for (int mt = 0; mt < 2; mt++)
#pragma unroll
                    for (int nt = 0; nt < 4; nt++) {
                        mmaH(D[mt][nt][0], D[mt][nt][1], A[mt][0], B1h[0][nt],
                             bias1p[nt], bias1p[nt]);
                        mmaH(D[mt][nt][0], D[mt][nt][1], A[mt][1], B1h[1][nt],
                             D[mt][nt][0], D[mt][nt][1]);
                    }

#pragma unroll
                for (int mt = 0; mt < 2; mt++) {
                    A[mt][0][0] = hrelu2(D[mt][0][0]);
                    A[mt][0][1] = hrelu2(D[mt][0][1]);
                    A[mt][0][2] = hrelu2(D[mt][1][0]);
                    A[mt][0][3] = hrelu2(D[mt][1][1]);
                    A[mt][1][0] = hrelu2(D[mt][2][0]);
                    A[mt][1][1] = hrelu2(D[mt][2][1]);
                    A[mt][1][2] = hrelu2(D[mt][3][0]);
                    A[mt][1][3] = hrelu2(D[mt][3][1]);
                }

#pragma unroll
                for (int mt = 0; mt < 2; mt++)
#pragma unroll
                    for (int nt = 0; nt < 4; nt++) {
                        mmaH(D[mt][nt][0], D[mt][nt][1], A[mt][0], B2h[0][nt],
                             bias2p[nt], bias2p[nt]);
                        mmaH(D[mt][nt][0], D[mt][nt][1], A[mt][1], B2h[1][nt],
                             D[mt][nt][0], D[mt][nt][1]);
                    }

#pragma unroll
                for (int nt = 0; nt < 4; nt++) {
                    uint32_t s01 = hadd2(hrelu2(D[0][nt][0]), hrelu2(D[0][nt][1]));
                    uint32_t s23 = hadd2(hrelu2(D[1][nt][0]), hrelu2(D[1][nt][1]));
                    uint32_t s = hadd2(s01, s23);
                    float lo, hi;
                    unpackH(s, lo, hi);
                    accE[nt] += lo;
                    accO[nt] += hi;
                }
                i++;
            }
            if (u < u1) { jt++; i = 0; }
        }

#pragma unroll
        for (int nt = 0; nt < 4; nt++) {
#pragma unroll
            for (int o = 4; o < 32; o <<= 1) {
                accE[nt] += __shfl_xor_sync(0xffffffffu, accE[nt], o);
                accO[nt] += __shfl_xor_sync(0xffffffffu, accO[nt], o);
            }
        }
        if (lane < 4) {
#pragma unroll
            for (int nt = 0; nt < 4; nt++) {
                g_part[w * HID + 8 * nt + 2 * lane + 0] = accE[nt];
                g_part[w * HID + 8 * nt + 2 * lane + 1] = accO[nt];
            }
        }
    }
    grid_barrier(tid);

    // ================= Phase 2a: stage-A reduce (CTAs 0..31) =================
    if (blockIdx.x < 32) {
        int k = lane;
        int sub = warp;                      // 0..3
        int r0 = blockIdx.x * 37;            // 32*37 = 1184 = NW
        float lsum = 0.f;
        for (int r = r0 + sub; r < r0 + 37; r += 4)
            lsum += g_part[r * HID + k];
        tmpA[sub][k] = lsum;
    }
    __syncthreads();
    if (blockIdx.x < 32 && tid < HID)
        g_q[blockIdx.x * HID + tid] = tmpA[0][tid] + tmpA[1][tid]
                                    + tmpA[2][tid] + tmpA[3][tid];
    grid_barrier(tid);

    // ================= Phase 2b: final reduce + head (CTA 0) =================
    if (blockIdx.x == 0) {
        int k = lane, sub = warp;
        float lsum = 0.f;
#pragma unroll
        for (int r = sub; r < 32; r += 4)
            lsum += g_q[r * HID + k];
        tmpA[sub][k] = lsum;
        __syncthreads();
        if (tid < HID)
            sS[tid] = tmpA[0][tid] + tmpA[1][tid] + tmpA[2][tid] + tmpA[3][tid];
        __syncthreads();
        if (tid < HID) {
            float t = bp[tid];
#pragma unroll
            for (int kk = 0; kk < HID; kk++)
                t = fmaf(sS[kk], Wp[kk * HID + tid], t);
            sP[tid] = fmaxf(t, 0.f);
        }
        __syncthreads();
        if (tid < HID) {
            float t = bo[tid];
#pragma unroll
            for (int kk = 0; kk < HID; kk++)
                t = fmaf(sP[kk], Wo[kk * HID + tid], t);
            out[tid] = t;
        }
    }
}

// ---------------------------------------------------------------------------
extern "C" void kernel_launch(void* const* d_in, const int* in_sizes, int n_in,
                              void* d_out, int out_size) {
    const float* x  = (const float*)d_in[0];
    const float* W0 = (const float*)d_in[1];
    const float* b0 = (const float*)d_in[2];
    const float* W1 = (const float*)d_in[3];
    const float* b1 = (const float*)d_in[4];
    const float* W2 = (const float*)d_in[5];
    const float* b2 = (const float*)d_in[6];
    const float* Wp = (const float*)d_in[7];
    const float* bp = (const float*)d_in[8];
    const float* Wo = (const float*)d_in[9];
    const float* bo = (const float*)d_in[10];
    float* out = (float*)d_out;

    fused_kernel<<<NCTA, 128>>>(x, W0, b0, W1, b1, W2, b2, Wp, bp, Wo, bo, out);
}